// round 1
// baseline (speedup 1.0000x reference)
#include <cuda_runtime.h>
#include <cstdint>

// Problem constants (fixed by the dataset: x[32768,2048] fp32, bank[20,2048] fp32)
constexpr int FEA      = 2048;
constexpr int NBANK    = 20;
constexpr int RPW      = 4;              // rows per warp
constexpr int NWARP    = 8;
constexpr int RPB      = RPW * NWARP;    // 32 rows per CTA
constexpr int NTHREADS = 256;
constexpr int KC       = 128;            // k-columns per chunk (32 lanes * float4)
constexpr int NCHUNK   = FEA / KC;       // 16
constexpr float LAMBDA = 0.0025f;
constexpr int SMEM_BYTES = NBANK * FEA * (int)sizeof(float);  // 163840

__device__ __forceinline__ float tanh_fast(float v) {
    float r;
    asm("tanh.approx.f32 %0, %1;" : "=f"(r) : "f"(v));
    return r;
}

extern __shared__ float s_bank[];  // [NBANK][FEA]

__global__ __launch_bounds__(NTHREADS, 1)
void memunit_fused(const float* __restrict__ x,
                   const float* __restrict__ bank,
                   float* __restrict__ out,
                   int n_tiles)
{
    const int tid = threadIdx.x;

    // Cooperative, coalesced bank -> SMEM load (once per persistent CTA)
    for (int i = tid; i < NBANK * FEA / 4; i += NTHREADS)
        reinterpret_cast<float4*>(s_bank)[i] =
            reinterpret_cast<const float4*>(bank)[i];
    __syncthreads();

    const int warp = tid >> 5;
    const int lane = tid & 31;

    for (int tile = blockIdx.x; tile < n_tiles; tile += gridDim.x) {
        const long row0 = (long)tile * RPB + warp * RPW;
        const float* xp = x + row0 * FEA + lane * 4;

        // ---------------- GEMM1: acc[r][j] = x[row r] . bank[j] ----------------
        float acc[RPW][NBANK];
        #pragma unroll
        for (int r = 0; r < RPW; r++)
            #pragma unroll
            for (int j = 0; j < NBANK; j++) acc[r][j] = 0.f;

        // software-pipelined x prefetch (next chunk loaded while FMAs run)
        float4 xv[RPW];
        #pragma unroll
        for (int r = 0; r < RPW; r++)
            xv[r] = *reinterpret_cast<const float4*>(xp + r * FEA);

        #pragma unroll 1
        for (int kc = 0; kc < NCHUNK; kc++) {
            float4 cur[RPW];
            #pragma unroll
            for (int r = 0; r < RPW; r++) cur[r] = xv[r];

            const int nk = (kc + 1) & (NCHUNK - 1);   // wrap: harmless re-read on last iter
            #pragma unroll
            for (int r = 0; r < RPW; r++)
                xv[r] = *reinterpret_cast<const float4*>(xp + r * FEA + nk * KC);

            const int kb = kc * KC + lane * 4;
            #pragma unroll
            for (int j = 0; j < NBANK; j++) {
                const float4 b = *reinterpret_cast<const float4*>(&s_bank[j * FEA + kb]);
                #pragma unroll
                for (int r = 0; r < RPW; r++) {
                    acc[r][j] = fmaf(cur[r].x, b.x, acc[r][j]);
                    acc[r][j] = fmaf(cur[r].y, b.y, acc[r][j]);
                    acc[r][j] = fmaf(cur[r].z, b.z, acc[r][j]);
                    acc[r][j] = fmaf(cur[r].w, b.w, acc[r][j]);
                }
            }
        }

        // ---------------- cross-lane reduction (butterfly: all lanes get sums) --
        #pragma unroll
        for (int r = 0; r < RPW; r++)
            #pragma unroll
            for (int j = 0; j < NBANK; j++) {
                float v = acc[r][j];
                v += __shfl_xor_sync(0xffffffffu, v, 16);
                v += __shfl_xor_sync(0xffffffffu, v, 8);
                v += __shfl_xor_sync(0xffffffffu, v, 4);
                v += __shfl_xor_sync(0xffffffffu, v, 2);
                v += __shfl_xor_sync(0xffffffffu, v, 1);
                acc[r][j] = v;
            }

        // ---------------- softmax -> softshrink -> softmax (per row, in regs) --
        #pragma unroll
        for (int r = 0; r < RPW; r++) {
            float m = acc[r][0];
            #pragma unroll
            for (int j = 1; j < NBANK; j++) m = fmaxf(m, acc[r][j]);

            float s = 0.f;
            #pragma unroll
            for (int j = 0; j < NBANK; j++) {
                const float e = __expf(acc[r][j] - m);
                acc[r][j] = e;
                s += e;
            }
            const float inv = 1.0f / s;

            // att >= 0, so softshrink(att) = max(att - lambda, 0)
            float m2 = 0.f;
            #pragma unroll
            for (int j = 0; j < NBANK; j++) {
                float a = fmaxf(acc[r][j] * inv - LAMBDA, 0.f);
                acc[r][j] = a;
                m2 = fmaxf(m2, a);
            }

            float s2 = 0.f;
            #pragma unroll
            for (int j = 0; j < NBANK; j++) {
                const float e = __expf(acc[r][j] - m2);
                acc[r][j] = e;
                s2 += e;
            }
            const float inv2 = 1.0f / s2;
            #pragma unroll
            for (int j = 0; j < NBANK; j++) acc[r][j] *= inv2;
        }

        // ---------------- GEMM2 + tanh: out[r][:] = tanh(att[r] @ bank) --------
        float* op = out + row0 * FEA + lane * 4;
        #pragma unroll 1
        for (int cc = 0; cc < NCHUNK; cc++) {
            const int cb = cc * KC + lane * 4;
            float4 o[RPW];
            #pragma unroll
            for (int r = 0; r < RPW; r++) o[r] = make_float4(0.f, 0.f, 0.f, 0.f);

            #pragma unroll
            for (int j = 0; j < NBANK; j++) {
                const float4 b = *reinterpret_cast<const float4*>(&s_bank[j * FEA + cb]);
                #pragma unroll
                for (int r = 0; r < RPW; r++) {
                    o[r].x = fmaf(acc[r][j], b.x, o[r].x);
                    o[r].y = fmaf(acc[r][j], b.y, o[r].y);
                    o[r].z = fmaf(acc[r][j], b.z, o[r].z);
                    o[r].w = fmaf(acc[r][j], b.w, o[r].w);
                }
            }

            #pragma unroll
            for (int r = 0; r < RPW; r++) {
                o[r].x = tanh_fast(o[r].x);
                o[r].y = tanh_fast(o[r].y);
                o[r].z = tanh_fast(o[r].z);
                o[r].w = tanh_fast(o[r].w);
                *reinterpret_cast<float4*>(op + r * FEA + cc * KC) = o[r];
            }
        }
    }
}

extern "C" void kernel_launch(void* const* d_in, const int* in_sizes, int n_in,
                              void* d_out, int out_size)
{
    const float* x    = reinterpret_cast<const float*>(d_in[0]);
    const float* bank = reinterpret_cast<const float*>(d_in[1]);
    float* out        = reinterpret_cast<float*>(d_out);

    const int rows    = in_sizes[0] / FEA;   // 32768
    const int n_tiles = rows / RPB;          // 1024 (exact)

    // Immediate host-side calls (not stream ops) — safe under graph capture.
    cudaFuncSetAttribute(memunit_fused,
                         cudaFuncAttributeMaxDynamicSharedMemorySize, SMEM_BYTES);

    int dev = 0, sms = 148;
    cudaGetDevice(&dev);
    cudaDeviceGetAttribute(&sms, cudaDevAttrMultiProcessorCount, dev);

    int grid = (sms < n_tiles) ? sms : n_tiles;   // persistent: 1 CTA/SM (160KB smem)
    memunit_fused<<<grid, NTHREADS, SMEM_BYTES>>>(x, bank, out, n_tiles);
}